// round 16
// baseline (speedup 1.0000x reference)
#include <cuda_runtime.h>
#include <cuda_fp16.h>
#include <cstdint>

#define BB    64
#define NNODE 1024
#define IND   512
#define HIDD  1024
#define LATD  256
#define TOK   (BB * NNODE)   // 65536

// ---------------------------------------------------------------------------
// Scratch (device globals — allocation is forbidden)
// ---------------------------------------------------------------------------
__device__ float g_d[TOK];
__device__ __align__(16) __half g_ah[(size_t)BB * NNODE * NNODE];   // a, fp16
__device__ __align__(16) __half g_xt[(size_t)BB * IND * NNODE];     // d_j * x^T
__device__ __align__(16) __half g_h[(size_t)TOK * IND];
__device__ __align__(16) __half g_h1[(size_t)TOK * HIDD];
__device__ __align__(16) __half g_w1[HIDD * IND];
__device__ __align__(16) __half g_wcat[2 * LATD * HIDD];            // [Wmu; Wlv]

// ---------------------------------------------------------------------------
// helpers (baseline PTX only)
// ---------------------------------------------------------------------------
__device__ __forceinline__ uint32_t smem_u32(const void* p) {
    uint32_t a;
    asm("{ .reg .u64 t; cvta.to.shared.u64 t, %1; cvt.u32.u64 %0, t; }" : "=r"(a) : "l"(p));
    return a;
}
__device__ __forceinline__ void ldsm4(uint32_t addr, uint32_t* r) {
    asm volatile("ldmatrix.sync.aligned.m8n8.x4.shared.b16 {%0,%1,%2,%3}, [%4];"
                 : "=r"(r[0]), "=r"(r[1]), "=r"(r[2]), "=r"(r[3]) : "r"(addr));
}
__device__ __forceinline__ void mma16816(float* c, const uint32_t* a, const uint32_t* b) {
    asm volatile(
        "mma.sync.aligned.m16n8k16.row.col.f32.f16.f16.f32 "
        "{%0,%1,%2,%3}, {%4,%5,%6,%7}, {%8,%9}, {%0,%1,%2,%3};"
        : "+f"(c[0]), "+f"(c[1]), "+f"(c[2]), "+f"(c[3])
        : "r"(a[0]), "r"(a[1]), "r"(a[2]), "r"(a[3]), "r"(b[0]), "r"(b[1]));
}
__device__ __forceinline__ void cpasync16(uint32_t dst, const void* src) {
    asm volatile("cp.async.cg.shared.global [%0], [%1], 16;" :: "r"(dst), "l"(src) : "memory");
}
#define CP_COMMIT() asm volatile("cp.async.commit_group;" ::: "memory")
#define CP_WAIT0()  asm volatile("cp.async.wait_group 0;" ::: "memory")
#define CP_WAIT1()  asm volatile("cp.async.wait_group 1;" ::: "memory")

// ---------------------------------------------------------------------------
// Fused conversions: blocks [0, TOK/8): a -> fp16 + degree factors
//                    blocks [TOK/8, +1024): W1/Wmu/Wlv -> fp16
// ---------------------------------------------------------------------------
#define ABLK (TOK / 8)                    // 8192
#define W1_F4   (HIDD * IND / 4)          // 131072
#define WHD_F4  (LATD * HIDD / 4)         // 65536
#define WBLK ((W1_F4 + 2 * WHD_F4) / 256) // 1024

__global__ void __launch_bounds__(256) conv_kernel(const float* __restrict__ a,
                                                   const float* __restrict__ W1,
                                                   const float* __restrict__ Wmu,
                                                   const float* __restrict__ Wlv) {
    if (blockIdx.x < ABLK) {
        int warp = (blockIdx.x * 256 + threadIdx.x) >> 5;
        int lane = threadIdx.x & 31;
        const float4* row = (const float4*)(a + (size_t)warp * NNODE);
        __half2* o = (__half2*)(g_ah + (size_t)warp * NNODE);
        float s = 0.f;
#pragma unroll
        for (int j = 0; j < 8; j++) {
            int i4 = lane + j * 32;
            float4 v = row[i4];
            s += v.x + v.y + v.z + v.w;
            o[2 * i4]     = __floats2half2_rn(v.x, v.y);
            o[2 * i4 + 1] = __floats2half2_rn(v.z, v.w);
        }
#pragma unroll
        for (int off = 16; off; off >>= 1) s += __shfl_xor_sync(0xffffffffu, s, off);
        if (lane == 0) g_d[warp] = rsqrtf(s + 1.0f + 1e-8f);
    } else {
        size_t i = (size_t)(blockIdx.x - ABLK) * 256 + threadIdx.x;
        const float* src; __half* dst; size_t o;
        if (i < W1_F4)               { src = W1;  dst = g_w1;   o = i; }
        else if (i < W1_F4 + WHD_F4) { src = Wmu; dst = g_wcat; o = i - W1_F4; }
        else                         { src = Wlv; dst = g_wcat + (size_t)LATD * HIDD;
                                       o = i - W1_F4 - WHD_F4; }
        float4 v = ((const float4*)src)[o];
        ((__half2*)dst)[2 * o]     = __floats2half2_rn(v.x, v.y);
        ((__half2*)dst)[2 * o + 1] = __floats2half2_rn(v.z, v.w);
    }
}

// ---------------------------------------------------------------------------
// Kernel: xt[b,c,j] = fp16(d[b,j] * x[b,j,c])  (transposed)
// ---------------------------------------------------------------------------
__global__ void __launch_bounds__(256) split_xt_kernel(const float* __restrict__ x) {
    __shared__ float t[32][33];
    int b  = blockIdx.z;
    int j0 = blockIdx.y * 32;
    int c0 = blockIdx.x * 32;
    int tx = threadIdx.x, ty = threadIdx.y;      // (32, 8)
#pragma unroll
    for (int k = 0; k < 4; k++) {
        int j = j0 + ty + k * 8;
        float dv = g_d[b * NNODE + j];
        t[ty + k * 8][tx] = x[((size_t)(b * NNODE + j)) * IND + c0 + tx] * dv;
    }
    __syncthreads();
#pragma unroll
    for (int k = 0; k < 4; k++) {
        int c = c0 + ty + k * 8;
        int j = j0 + tx;
        g_xt[((size_t)b * IND + c) * NNODE + j] = __float2half_rn(t[tx][ty + k * 8]);
    }
}

// ---------------------------------------------------------------------------
// Pure fp16 GEMM via mma.sync (HMMA): D[m,n] = sum_k A[m,k]*B[n,k]
// R12 config: CTA 128x128, 256 threads, warp grid 4Mx2N, warp tile 32x64.
// KC=64, 3-stage cp.async pipeline; 128B smem rows, swizzle (seg+row)&7.
// Staging addresses fully precomputed: swizzle term is i-invariant (32%8==0),
// so each thread has ONE smem offset + compile-time i*4096, and ONE global
// pointer + compile-time i*32*KDIM + kk.  (kills per-chunk staging ALU)
// EPI: 0 = message passing (d_m scale + d_m^2*x diag, fp16 out)
//      1 = bias + relu (fp16 out)
//      3 = dual-head bias (cols<256 -> mu else logvar), fp32 out
// ---------------------------------------------------------------------------
#define TILE_B 16384
#define BUF_B  32768
#define GEMM_SMEM 98304
#define STG_STRIDE 272      // (128+8) fp16 per row (epilogue restage)

template <int KDIM, int EPI, int LDO>
__global__ void __launch_bounds__(256, 2) gemm_k(
    const __half* __restrict__ A,
    const __half* __restrict__ B,
    long bstride,
    float* __restrict__ outf,
    __half* __restrict__ oh,
    const float* __restrict__ bias, const float* __restrict__ bias2,
    const float* __restrict__ xdiag)
{
    extern __shared__ char smem_raw[];
    const uint32_t sb  = smem_u32(smem_raw);
    const int tid  = threadIdx.x;
    const int wid  = tid >> 5;
    const int lane = tid & 31;
    const int n0   = blockIdx.x * 128;
    const int m0   = blockIdx.y * 128;
    const int wm   = wid & 3;       // 4 warps in M (32 rows)
    const int wn   = wid >> 2;      // 2 warps in N (64 cols)

    const __half* Bb = B + (bstride ? (long)(m0 >> 10) * bstride : 0);

    float acc[2][8][4];
#pragma unroll
    for (int i = 0; i < 2; i++)
#pragma unroll
        for (int j = 0; j < 8; j++)
#pragma unroll
            for (int k = 0; k < 4; k++) acc[i][j][k] = 0.f;

    // ---- precomputed staging addresses (per thread) ----
    const int srow = tid >> 3;             // 0..31
    const int sseg = tid & 7;              // 0..7
    const uint32_t st_off = (uint32_t)(srow * 128 + (((sseg + srow) & 7) << 4));
    const __half* Ap = A  + (size_t)(m0 + srow) * KDIM + sseg * 8;
    const __half* Bp = Bb + (size_t)(n0 + srow) * KDIM + sseg * 8;

    // ldmatrix per-lane constants (128B rows; swizzle term = row & 7)
    const int a_row  = wm * 32 + (lane & 15);
    const int a_sw0  = (lane >> 4) + a_row;
    const uint32_t a_base = (uint32_t)(a_row * 128);
    const int b_row  = wn * 64 + ((lane >> 4) << 3) + (lane & 7);
    const int b_sw0  = ((lane >> 3) & 1) + b_row;
    const uint32_t b_base = (uint32_t)(b_row * 128);

    const int NC = KDIM / 64;

    auto stage = [&](int kk, uint32_t buf) {
#pragma unroll
        for (int i = 0; i < 4; i++)
            cpasync16(buf + st_off + i * 4096, Ap + kk + (size_t)i * 32 * KDIM);
#pragma unroll
        for (int i = 0; i < 4; i++)
            cpasync16(buf + TILE_B + st_off + i * 4096, Bp + kk + (size_t)i * 32 * KDIM);
        CP_COMMIT();
    };

    // prologue: two chunks in flight
    stage(0, sb);
    if (NC > 1) stage(64, sb + BUF_B);

    int bufidx = 0;
    for (int t = 0; t < NC; t++) {
        if (t == NC - 1) { CP_WAIT0(); } else { CP_WAIT1(); }
        __syncthreads();

        if (t + 2 < NC) {
            int nb = bufidx + 2; if (nb >= 3) nb -= 3;
            stage((t + 2) * 64, sb + (uint32_t)nb * BUF_B);
        }

        const uint32_t base = sb + (uint32_t)bufidx * BUF_B;
        if (++bufidx == 3) bufidx = 0;

#pragma unroll
        for (int ks = 0; ks < 4; ks++) {
            const uint32_t aswk = (uint32_t)(((a_sw0 + ks * 2) & 7) << 4);
            const uint32_t bswk = (uint32_t)(((b_sw0 + ks * 2) & 7) << 4);
            uint32_t ah[2][4];
#pragma unroll
            for (int tm = 0; tm < 2; tm++)
                ldsm4(base + a_base + tm * 2048 + aswk, ah[tm]);
#pragma unroll
            for (int tnp = 0; tnp < 4; tnp++) {
                uint32_t bh[4];
                ldsm4(base + TILE_B + b_base + tnp * 2048 + bswk, bh);
#pragma unroll
                for (int tm = 0; tm < 2; tm++)
#pragma unroll
                    for (int hf = 0; hf < 2; hf++)
                        mma16816(acc[tm][tnp * 2 + hf], ah[tm], bh + hf * 2);
            }
        }
    }

    if (EPI == 3) {
#pragma unroll
        for (int tm = 0; tm < 2; tm++)
#pragma unroll
            for (int hf = 0; hf < 2; hf++) {
                const int row = m0 + wm * 32 + tm * 16 + hf * 8 + (lane >> 2);
#pragma unroll
                for (int tn = 0; tn < 8; tn++) {
                    const int col = n0 + wn * 64 + tn * 8 + (lane & 3) * 2;
                    float v0 = acc[tm][tn][hf * 2 + 0];
                    float v1 = acc[tm][tn][hf * 2 + 1];
                    const float* bp = (col < LATD) ? (bias + col) : (bias2 + col - LATD);
                    float2 bv = *(const float2*)bp;
                    v0 += bv.x; v1 += bv.y;
                    float* dst = (col < LATD)
                        ? (outf + (size_t)row * LATD + col)
                        : (outf + (size_t)TOK * LATD + (size_t)row * LATD + (col - LATD));
                    *(float2*)dst = make_float2(v0, v1);
                }
            }
        return;
    }

    // EPI 0/1: epilogue math, SMEM restage (fp16), 16B/lane stores
    __syncthreads();
    char* st = smem_raw;                 // 128 * 272 = 34816 <= 98304
#pragma unroll
    for (int tm = 0; tm < 2; tm++) {
#pragma unroll
        for (int hf = 0; hf < 2; hf++) {
            const int rl = wm * 32 + tm * 16 + hf * 8 + (lane >> 2);
            const int row = m0 + rl;
            float di = 0.f, d2 = 0.f;
            if (EPI == 0) { di = g_d[row]; d2 = di * di; }
#pragma unroll
            for (int tn = 0; tn < 8; tn++) {
                const int cl = wn * 64 + tn * 8 + (lane & 3) * 2;
                float v0 = acc[tm][tn][hf * 2 + 0];
                float v1 = acc[tm][tn][hf * 2 + 1];
                if (EPI == 0) {
                    float2 xv = *(const float2*)(xdiag + (size_t)row * LDO + n0 + cl);
                    v0 = di * v0 + d2 * xv.x;
                    v1 = di * v1 + d2 * xv.y;
                } else {
                    float2 bv = *(const float2*)(bias + n0 + cl);
                    v0 = fmaxf(v0 + bv.x, 0.f);
                    v1 = fmaxf(v1 + bv.y, 0.f);
                }
                *(__half2*)(st + rl * STG_STRIDE + cl * 2) = __floats2half2_rn(v0, v1);
            }
        }
    }
    __syncthreads();
#pragma unroll
    for (int it = 0; it < 8; it++) {
        int lin = it * 256 + tid;        // 0..2047
        int r   = lin >> 4;              // 0..127
        int c16 = lin & 15;              // 16B segment (128 fp16 = 16 segs)
        uint4 v = *(uint4*)(st + r * STG_STRIDE + c16 * 16);
        *(uint4*)(oh + (size_t)(m0 + r) * LDO + n0 + c16 * 8) = v;
    }
}

// ---------------------------------------------------------------------------
extern "C" void kernel_launch(void* const* d_in, const int* in_sizes, int n_in,
                              void* d_out, int out_size) {
    const float* x   = (const float*)d_in[0];
    const float* a   = (const float*)d_in[1];
    const float* W1  = (const float*)d_in[2];
    const float* b1  = (const float*)d_in[3];
    const float* Wmu = (const float*)d_in[4];
    const float* bmu = (const float*)d_in[5];
    const float* Wlv = (const float*)d_in[6];
    const float* blv = (const float*)d_in[7];
    float* out = (float*)d_out;

    cudaFuncSetAttribute(gemm_k<NNODE, 0, IND>,  cudaFuncAttributeMaxDynamicSharedMemorySize, GEMM_SMEM);
    cudaFuncSetAttribute(gemm_k<IND,   1, HIDD>, cudaFuncAttributeMaxDynamicSharedMemorySize, GEMM_SMEM);
    cudaFuncSetAttribute(gemm_k<HIDD,  3, LATD>, cudaFuncAttributeMaxDynamicSharedMemorySize, GEMM_SMEM);

    __half *ah, *xt, *h, *h1, *w1, *wc;
    cudaGetSymbolAddress((void**)&ah, g_ah);
    cudaGetSymbolAddress((void**)&xt, g_xt);
    cudaGetSymbolAddress((void**)&h,  g_h);
    cudaGetSymbolAddress((void**)&h1, g_h1);
    cudaGetSymbolAddress((void**)&w1, g_w1);
    cudaGetSymbolAddress((void**)&wc, g_wcat);

    // #1 fused: a->fp16 + degree  AND  weight conversions
    conv_kernel<<<ABLK + WBLK, 256>>>(a, W1, Wmu, Wlv);
    // #2 x transpose + d_j scale -> fp16
    split_xt_kernel<<<dim3(IND / 32, NNODE / 32, BB), dim3(32, 8)>>>(x);
    // #3 message passing GEMM: h = a_norm @ x
    gemm_k<NNODE, 0, IND><<<dim3(IND / 128, TOK / 128), 256, GEMM_SMEM>>>(
        ah, xt, (long)IND * NNODE, nullptr, h, nullptr, nullptr, x);
    // #4 h1 = relu(h @ W1^T + b1)
    gemm_k<IND, 1, HIDD><<<dim3(HIDD / 128, TOK / 128), 256, GEMM_SMEM>>>(
        h, w1, 0, nullptr, h1, b1, nullptr, nullptr);
    // #5 fused mu+logvar heads: one N=512 GEMM over [Wmu; Wlv]
    gemm_k<HIDD, 3, LATD><<<dim3((2 * LATD) / 128, TOK / 128), 256, GEMM_SMEM>>>(
        h1, wc, 0, out, nullptr, bmu, blv, nullptr);
}

// round 17
// speedup vs baseline: 1.0055x; 1.0055x over previous
#include <cuda_runtime.h>
#include <cuda_fp16.h>
#include <cstdint>

#define BB    64
#define NNODE 1024
#define IND   512
#define HIDD  1024
#define LATD  256
#define TOK   (BB * NNODE)   // 65536

// ---------------------------------------------------------------------------
// Scratch (device globals — allocation is forbidden)
// ---------------------------------------------------------------------------
__device__ float g_d[TOK];
__device__ __align__(16) __half g_ah[(size_t)BB * NNODE * NNODE];   // a, fp16
__device__ __align__(16) __half g_xh[(size_t)TOK * IND];            // d_j*x, [j,c]
__device__ __align__(16) __half g_h[(size_t)TOK * IND];
__device__ __align__(16) __half g_h1[(size_t)TOK * HIDD];
__device__ __align__(16) __half g_w1[HIDD * IND];
__device__ __align__(16) __half g_wcat[2 * LATD * HIDD];            // [Wmu; Wlv]

// ---------------------------------------------------------------------------
// helpers (baseline PTX only)
// ---------------------------------------------------------------------------
__device__ __forceinline__ uint32_t smem_u32(const void* p) {
    uint32_t a;
    asm("{ .reg .u64 t; cvta.to.shared.u64 t, %1; cvt.u32.u64 %0, t; }" : "=r"(a) : "l"(p));
    return a;
}
__device__ __forceinline__ void ldsm4(uint32_t addr, uint32_t* r) {
    asm volatile("ldmatrix.sync.aligned.m8n8.x4.shared.b16 {%0,%1,%2,%3}, [%4];"
                 : "=r"(r[0]), "=r"(r[1]), "=r"(r[2]), "=r"(r[3]) : "r"(addr));
}
__device__ __forceinline__ void ldsm4t(uint32_t addr, uint32_t* r) {
    asm volatile("ldmatrix.sync.aligned.m8n8.x4.trans.shared.b16 {%0,%1,%2,%3}, [%4];"
                 : "=r"(r[0]), "=r"(r[1]), "=r"(r[2]), "=r"(r[3]) : "r"(addr));
}
__device__ __forceinline__ void mma16816(float* c, const uint32_t* a, const uint32_t* b) {
    asm volatile(
        "mma.sync.aligned.m16n8k16.row.col.f32.f16.f16.f32 "
        "{%0,%1,%2,%3}, {%4,%5,%6,%7}, {%8,%9}, {%0,%1,%2,%3};"
        : "+f"(c[0]), "+f"(c[1]), "+f"(c[2]), "+f"(c[3])
        : "r"(a[0]), "r"(a[1]), "r"(a[2]), "r"(a[3]), "r"(b[0]), "r"(b[1]));
}
__device__ __forceinline__ void cpasync16(uint32_t dst, const void* src) {
    asm volatile("cp.async.cg.shared.global [%0], [%1], 16;" :: "r"(dst), "l"(src) : "memory");
}
#define CP_COMMIT() asm volatile("cp.async.commit_group;" ::: "memory")
#define CP_WAIT0()  asm volatile("cp.async.wait_group 0;" ::: "memory")
#define CP_WAIT1()  asm volatile("cp.async.wait_group 1;" ::: "memory")

// ---------------------------------------------------------------------------
// Fused conversions:
//   blocks [0, ABLK): a row -> fp16, degree d, AND d*x row -> fp16 (coalesced;
//                     butterfly reduction leaves rowsum in every lane)
//   blocks [ABLK, +WBLK): W1/Wmu/Wlv -> fp16
// ---------------------------------------------------------------------------
#define ABLK (TOK / 8)                    // 8192
#define W1_F4   (HIDD * IND / 4)          // 131072
#define WHD_F4  (LATD * HIDD / 4)         // 65536
#define WBLK ((W1_F4 + 2 * WHD_F4) / 256) // 1024

__global__ void __launch_bounds__(256) conv_kernel(const float* __restrict__ a,
                                                   const float* __restrict__ x,
                                                   const float* __restrict__ W1,
                                                   const float* __restrict__ Wmu,
                                                   const float* __restrict__ Wlv) {
    if (blockIdx.x < ABLK) {
        int warp = (blockIdx.x * 256 + threadIdx.x) >> 5;
        int lane = threadIdx.x & 31;
        const float4* row = (const float4*)(a + (size_t)warp * NNODE);
        __half2* o = (__half2*)(g_ah + (size_t)warp * NNODE);
        float s = 0.f;
#pragma unroll
        for (int j = 0; j < 8; j++) {
            int i4 = lane + j * 32;
            float4 v = row[i4];
            s += v.x + v.y + v.z + v.w;
            o[2 * i4]     = __floats2half2_rn(v.x, v.y);
            o[2 * i4 + 1] = __floats2half2_rn(v.z, v.w);
        }
#pragma unroll
        for (int off = 16; off; off >>= 1) s += __shfl_xor_sync(0xffffffffu, s, off);
        float dv = rsqrtf(s + 1.0f + 1e-8f);
        if (lane == 0) g_d[warp] = dv;
        // fused: xh[j,c] = fp16(d_j * x[j,c])  (j = warp)
        const float4* xr = (const float4*)(x + (size_t)warp * IND);
        __half2* xo = (__half2*)(g_xh + (size_t)warp * IND);
#pragma unroll
        for (int j = 0; j < 4; j++) {           // IND/4/32 = 4
            int i4 = lane + j * 32;
            float4 v = xr[i4];
            xo[2 * i4]     = __floats2half2_rn(v.x * dv, v.y * dv);
            xo[2 * i4 + 1] = __floats2half2_rn(v.z * dv, v.w * dv);
        }
    } else {
        size_t i = (size_t)(blockIdx.x - ABLK) * 256 + threadIdx.x;
        const float* src; __half* dst; size_t o;
        if (i < W1_F4)               { src = W1;  dst = g_w1;   o = i; }
        else if (i < W1_F4 + WHD_F4) { src = Wmu; dst = g_wcat; o = i - W1_F4; }
        else                         { src = Wlv; dst = g_wcat + (size_t)LATD * HIDD;
                                       o = i - W1_F4 - WHD_F4; }
        float4 v = ((const float4*)src)[o];
        ((__half2*)dst)[2 * o]     = __floats2half2_rn(v.x, v.y);
        ((__half2*)dst)[2 * o + 1] = __floats2half2_rn(v.z, v.w);
    }
}

// ---------------------------------------------------------------------------
// Pure fp16 GEMM via mma.sync (HMMA): D[m,n] = sum_k A[m,k]*B[n,k]
// CTA 128x128, 256 threads, warps 4Mx2N (tile 32x64), KC=64, 3-stage cp.async.
// BT=false: B stored K-major [n,k] (rows n, k contiguous), ldmatrix non-trans.
// BT=true : B stored [k,n] (rows k, n contiguous; e.g. xh), tile 64x256B,
//           swizzle (seg+row)&15, fragments via ldmatrix.trans — no transpose
//           pass needed for x.
// EPI: 0 = message passing (d_m scale + d_m^2*x diag, fp16 out)
//      1 = bias + relu (fp16 out)
//      3 = dual-head bias (cols<256 -> mu else logvar), fp32 out
// ---------------------------------------------------------------------------
#define TILE_B 16384
#define BUF_B  32768
#define GEMM_SMEM 98304
#define STG_STRIDE 272      // (128+8) fp16 per row (epilogue restage)

template <int KDIM, int EPI, int LDO, bool BT>
__global__ void __launch_bounds__(256, 2) gemm_k(
    const __half* __restrict__ A,
    const __half* __restrict__ B,
    long bstride,
    float* __restrict__ outf,
    __half* __restrict__ oh,
    const float* __restrict__ bias, const float* __restrict__ bias2,
    const float* __restrict__ xdiag)
{
    extern __shared__ char smem_raw[];
    const uint32_t sb  = smem_u32(smem_raw);
    const int tid  = threadIdx.x;
    const int wid  = tid >> 5;
    const int lane = tid & 31;
    const int n0   = blockIdx.x * 128;
    const int m0   = blockIdx.y * 128;
    const int wm   = wid & 3;       // 4 warps in M (32 rows)
    const int wn   = wid >> 2;      // 2 warps in N (64 cols)

    const __half* Bb = B + (bstride ? (long)(m0 >> 10) * bstride : 0);

    float acc[2][8][4];
#pragma unroll
    for (int i = 0; i < 2; i++)
#pragma unroll
        for (int j = 0; j < 8; j++)
#pragma unroll
            for (int k = 0; k < 4; k++) acc[i][j][k] = 0.f;

    // ---- A staging (both paths): 128 rows x 8 segs, swizzle (seg+row)&7 ----
    const int srow = tid >> 3;             // 0..31
    const int sseg = tid & 7;              // 0..7
    const uint32_t st_off = (uint32_t)(srow * 128 + (((sseg + srow) & 7) << 4));
    const __half* Ap = A + (size_t)(m0 + srow) * KDIM + sseg * 8;

    // ---- B staging ----
    // BT=false: same scheme as A.  BT=true: 64 rows(k) x 16 segs(n), 256B rows.
    const int srow_b = BT ? (tid >> 4) : srow;            // BT: 0..15
    const int sseg_b = BT ? (tid & 15) : sseg;
    const uint32_t st_off_b = BT
        ? (uint32_t)(srow_b * 256 + (((sseg_b + srow_b) & 15) << 4))
        : st_off;
    const __half* Bp = BT
        ? (Bb + (size_t)srow_b * LDO + n0 + sseg_b * 8)
        : (Bb + (size_t)(n0 + srow) * KDIM + sseg * 8);

    // ---- A fragment constants ----
    const int a_row  = wm * 32 + (lane & 15);
    const int a_sw0  = (lane >> 4) + a_row;
    const uint32_t a_base = (uint32_t)(a_row * 128);

    // ---- B fragment constants ----
    // BT=false (K-major): rows n, 128B, swizzle (seg+row)&7
    const int b_row  = wn * 64 + ((lane >> 4) << 3) + (lane & 7);
    const int b_sw0  = ((lane >> 3) & 1) + b_row;
    const uint32_t b_base = (uint32_t)(b_row * 128);
    // BT=true ([k,n]): row = ks*16 + (lane&15); nseg = wn*8 + tnp*2 + (lane>>4)
    const int bt_rl  = lane & 15;
    const uint32_t bt_row = (uint32_t)(bt_rl * 256);
    const int bt_sw0 = wn * 8 + (lane >> 4) + bt_rl;     // + tnp*2, &15 at use

    const int NC = KDIM / 64;

    auto stage = [&](int kk, uint32_t buf) {
#pragma unroll
        for (int i = 0; i < 4; i++)
            cpasync16(buf + st_off + i * 4096, Ap + kk + (size_t)i * 32 * KDIM);
        if (BT) {
#pragma unroll
            for (int i = 0; i < 4; i++)
                cpasync16(buf + TILE_B + st_off_b + i * 4096,
                          Bp + (size_t)(kk + i * 16) * LDO);
        } else {
#pragma unroll
            for (int i = 0; i < 4; i++)
                cpasync16(buf + TILE_B + st_off_b + i * 4096,
                          Bp + kk + (size_t)i * 32 * KDIM);
        }
        CP_COMMIT();
    };

    // prologue: two chunks in flight
    stage(0, sb);
    if (NC > 1) stage(64, sb + BUF_B);

    int bufidx = 0;
    for (int t = 0; t < NC; t++) {
        if (t == NC - 1) { CP_WAIT0(); } else { CP_WAIT1(); }
        __syncthreads();

        if (t + 2 < NC) {
            int nb = bufidx + 2; if (nb >= 3) nb -= 3;
            stage((t + 2) * 64, sb + (uint32_t)nb * BUF_B);
        }

        const uint32_t base = sb + (uint32_t)bufidx * BUF_B;
        if (++bufidx == 3) bufidx = 0;

#pragma unroll
        for (int ks = 0; ks < 4; ks++) {
            const uint32_t aswk = (uint32_t)(((a_sw0 + ks * 2) & 7) << 4);
            uint32_t ah[2][4];
#pragma unroll
            for (int tm = 0; tm < 2; tm++)
                ldsm4(base + a_base + tm * 2048 + aswk, ah[tm]);
#pragma unroll
            for (int tnp = 0; tnp < 4; tnp++) {
                uint32_t bh[4];
                if (BT) {
                    uint32_t segp = (uint32_t)(((bt_sw0 + tnp * 2) & 15) << 4);
                    ldsm4t(base + TILE_B + (uint32_t)(ks * 4096) + bt_row + segp, bh);
                } else {
                    const uint32_t bswk = (uint32_t)(((b_sw0 + ks * 2) & 7) << 4);
                    ldsm4(base + TILE_B + b_base + tnp * 2048 + bswk, bh);
                }
#pragma unroll
                for (int tm = 0; tm < 2; tm++)
#pragma unroll
                    for (int hf = 0; hf < 2; hf++)
                        mma16816(acc[tm][tnp * 2 + hf], ah[tm], bh + hf * 2);
            }
        }
    }

    if (EPI == 3) {
#pragma unroll
        for (int tm = 0; tm < 2; tm++)
#pragma unroll
            for (int hf = 0; hf < 2; hf++) {
                const int row = m0 + wm * 32 + tm * 16 + hf * 8 + (lane >> 2);
#pragma unroll
                for (int tn = 0; tn < 8; tn++) {
                    const int col = n0 + wn * 64 + tn * 8 + (lane & 3) * 2;
                    float v0 = acc[tm][tn][hf * 2 + 0];
                    float v1 = acc[tm][tn][hf * 2 + 1];
                    const float* bp = (col < LATD) ? (bias + col) : (bias2 + col - LATD);
                    float2 bv = *(const float2*)bp;
                    v0 += bv.x; v1 += bv.y;
                    float* dst = (col < LATD)
                        ? (outf + (size_t)row * LATD + col)
                        : (outf + (size_t)TOK * LATD + (size_t)row * LATD + (col - LATD));
                    *(float2*)dst = make_float2(v0, v1);
                }
            }
        return;
    }

    // EPI 0/1: epilogue math, SMEM restage (fp16), 16B/lane stores
    __syncthreads();
    char* st = smem_raw;                 // 128 * 272 = 34816 <= 98304
#pragma unroll
    for (int tm = 0; tm < 2; tm++) {
#pragma unroll
        for (int hf = 0; hf < 2; hf++) {
            const int rl = wm * 32 + tm * 16 + hf * 8 + (lane >> 2);
            const int row = m0 + rl;
            float di = 0.f, d2 = 0.f;
            if (EPI == 0) { di = g_d[row]; d2 = di * di; }
#pragma unroll
            for (int tn = 0; tn < 8; tn++) {
                const int cl = wn * 64 + tn * 8 + (lane & 3) * 2;
                float v0 = acc[tm][tn][hf * 2 + 0];
                float v1 = acc[tm][tn][hf * 2 + 1];
                if (EPI == 0) {
                    float2 xv = *(const float2*)(xdiag + (size_t)row * LDO + n0 + cl);
                    v0 = di * v0 + d2 * xv.x;
                    v1 = di * v1 + d2 * xv.y;
                } else {
                    float2 bv = *(const float2*)(bias + n0 + cl);
                    v0 = fmaxf(v0 + bv.x, 0.f);
                    v1 = fmaxf(v1 + bv.y, 0.f);
                }
                *(__half2*)(st + rl * STG_STRIDE + cl * 2) = __floats2half2_rn(v0, v1);
            }
        }
    }
    __syncthreads();
#pragma unroll
    for (int it = 0; it < 8; it++) {
        int lin = it * 256 + tid;        // 0..2047
        int r   = lin >> 4;              // 0..127
        int c16 = lin & 15;              // 16B segment (128 fp16 = 16 segs)
        uint4 v = *(uint4*)(st + r * STG_STRIDE + c16 * 16);
        *(uint4*)(oh + (size_t)(m0 + r) * LDO + n0 + c16 * 8) = v;
    }
}

// ---------------------------------------------------------------------------
extern "C" void kernel_launch(void* const* d_in, const int* in_sizes, int n_in,
                              void* d_out, int out_size) {
    const float* x   = (const float*)d_in[0];
    const float* a   = (const float*)d_in[1];
    const float* W1  = (const float*)d_in[2];
    const float* b1  = (const float*)d_in[3];
    const float* Wmu = (const float*)d_in[4];
    const float* bmu = (const float*)d_in[5];
    const float* Wlv = (const float*)d_in[6];
    const float* blv = (const float*)d_in[7];
    float* out = (float*)d_out;

    cudaFuncSetAttribute(gemm_k<NNODE, 0, IND, true>,   cudaFuncAttributeMaxDynamicSharedMemorySize, GEMM_SMEM);
    cudaFuncSetAttribute(gemm_k<IND,   1, HIDD, false>, cudaFuncAttributeMaxDynamicSharedMemorySize, GEMM_SMEM);
    cudaFuncSetAttribute(gemm_k<HIDD,  3, LATD, false>, cudaFuncAttributeMaxDynamicSharedMemorySize, GEMM_SMEM);

    __half *ah, *xh, *h, *h1, *w1, *wc;
    cudaGetSymbolAddress((void**)&ah, g_ah);
    cudaGetSymbolAddress((void**)&xh, g_xh);
    cudaGetSymbolAddress((void**)&h,  g_h);
    cudaGetSymbolAddress((void**)&h1, g_h1);
    cudaGetSymbolAddress((void**)&w1, g_w1);
    cudaGetSymbolAddress((void**)&wc, g_wcat);

    // #1 fused: a->fp16 + degree + d*x->fp16  AND  weight conversions
    conv_kernel<<<ABLK + WBLK, 256>>>(a, x, W1, Wmu, Wlv);
    // #2 message passing GEMM: h = a_norm @ x  (trans-B path, no transpose pass)
    gemm_k<NNODE, 0, IND, true><<<dim3(IND / 128, TOK / 128), 256, GEMM_SMEM>>>(
        ah, xh, (long)NNODE * IND, nullptr, h, nullptr, nullptr, x);
    // #3 h1 = relu(h @ W1^T + b1)
    gemm_k<IND, 1, HIDD, false><<<dim3(HIDD / 128, TOK / 128), 256, GEMM_SMEM>>>(
        h, w1, 0, nullptr, h1, b1, nullptr, nullptr);
    // #4 fused mu+logvar heads: one N=512 GEMM over [Wmu; Wlv]
    gemm_k<HIDD, 3, LATD, false><<<dim3((2 * LATD) / 128, TOK / 128), 256, GEMM_SMEM>>>(
        h1, wc, 0, out, nullptr, bmu, blv, nullptr);
}